// round 3
// baseline (speedup 1.0000x reference)
#include <cuda_runtime.h>
#include <cstdint>

#define NN 50000
#define EE 800000
#define GG 1024
#define DD 128
#define D2 256
#define LL 3
#define BNE 1e-5f

// ---------------- scratch (device globals: no allocation allowed) ----------
__device__ __align__(128) float g_h[NN * DD];     // node features (25.6 MB)
__device__ __align__(128) float g_agg[NN * DD];   // scatter accumulator (25.6 MB)
__device__ __align__(128) float g_y[NN * D2];     // hidden 2D activations (51.2 MB)
__device__ __align__(128) float g_vn[GG * DD];    // virtual-node state
__device__ __align__(128) float g_vt[GG * DD];    // per-graph segment sum
__device__ __align__(128) float g_t[GG * D2];     // vn-mlp hidden

// ---------------- packed f32x2 helpers (Blackwell FFMA2 via PTX) ----------
__device__ __forceinline__ unsigned long long pk2(float x, float y) {
    unsigned long long r;
    asm("mov.b64 %0, {%1, %2};" : "=l"(r)
        : "r"(__float_as_uint(x)), "r"(__float_as_uint(y)));
    return r;
}
__device__ __forceinline__ unsigned long long rep2(float x) {
    unsigned u = __float_as_uint(x);
    unsigned long long r;
    asm("mov.b64 %0, {%1, %1};" : "=l"(r) : "r"(u));
    return r;
}
__device__ __forceinline__ void fma2(unsigned long long& d, unsigned long long a,
                                     unsigned long long b) {
    asm("fma.rn.f32x2 %0, %1, %2, %0;" : "+l"(d) : "l"(a), "l"(b));
}
__device__ __forceinline__ float2 upk(unsigned long long p) {
    unsigned lo, hi;
    asm("mov.b64 {%0, %1}, %2;" : "=r"(lo), "=r"(hi) : "l"(p));
    return make_float2(__uint_as_float(lo), __uint_as_float(hi));
}

// ---------------- small elementwise kernels --------------------------------
__global__ void k_vn_init(const float* __restrict__ vn_emb0) {
    int g = blockIdx.x, d = threadIdx.x;
    g_vn[g * DD + d] = vn_emb0[d];
    g_vt[g * DD + d] = 0.0f;
}

__global__ void k_zero_vt() {
    g_vt[blockIdx.x * DD + threadIdx.x] = 0.0f;
}

// atom encoder fused with: layer-0 vn add (vn==vn_emb0 broadcast), agg zero,
// and layer-0 segment-sum accumulation into vt.
__global__ void k_atom(const int* __restrict__ x_atom,
                       const float* __restrict__ atom_emb,
                       const float* __restrict__ vn_emb0,
                       const int* __restrict__ batch) {
    int n = blockIdx.x, d = threadIdx.x;
    float s = vn_emb0[d];
#pragma unroll
    for (int f = 0; f < 9; ++f) {
        int idx = __ldg(&x_atom[n * 9 + f]);
        s += __ldg(&atom_emb[(f * 100 + idx) * DD + d]);
    }
    g_h[n * DD + d] = s;
    g_agg[n * DD + d] = 0.0f;
    atomicAdd(&g_vt[__ldg(&batch[n]) * DD + d], s);
}

// h += vn[batch]; zero agg; optionally accumulate segment sum into vt
template <bool ACC_VT>
__global__ void k_add_vn(const int* __restrict__ batch) {
    int n = blockIdx.x, d = threadIdx.x;
    int b = __ldg(&batch[n]);
    float v = g_h[n * DD + d] + g_vn[b * DD + d];
    g_h[n * DD + d] = v;
    g_agg[n * DD + d] = 0.0f;
    if (ACC_VT) atomicAdd(&g_vt[b * DD + d], v);
}

// ---------------- edge kernel: bond-enc + relu(h[src]+e) -> red.v4 --------
__global__ __launch_bounds__(256) void k_edge(const int* __restrict__ eidx,
                                              const int* __restrict__ eattr,
                                              const float* __restrict__ bond) {
    int e = blockIdx.x * 8 + (threadIdx.x >> 5);
    if (e >= EE) return;
    int lane = threadIdx.x & 31;
    int src = __ldg(eidx + e);
    int dst = __ldg(eidx + EE + e);
    int a0 = __ldg(eattr + 3 * e);
    int a1 = __ldg(eattr + 3 * e + 1);
    int a2 = __ldg(eattr + 3 * e + 2);
    float4 e0 = *(const float4*)(bond + (size_t)(0 * 10 + a0) * DD + lane * 4);
    float4 e1 = *(const float4*)(bond + (size_t)(1 * 10 + a1) * DD + lane * 4);
    float4 e2 = *(const float4*)(bond + (size_t)(2 * 10 + a2) * DD + lane * 4);
    float4 hv = *(const float4*)(g_h + (size_t)src * DD + lane * 4);
    float mx = fmaxf(hv.x + e0.x + e1.x + e2.x, 0.0f);
    float my = fmaxf(hv.y + e0.y + e1.y + e2.y, 0.0f);
    float mz = fmaxf(hv.z + e0.z + e1.z + e2.z, 0.0f);
    float mw = fmaxf(hv.w + e0.w + e1.w + e2.w, 0.0f);
    float* p = g_agg + (size_t)dst * DD + lane * 4;
    asm volatile("red.global.add.v4.f32 [%0], {%1,%2,%3,%4};"
                 :: "l"(p), "f"(mx), "f"(my), "f"(mz), "f"(mw) : "memory");
}

// ---------------- GEMM1: y = relu(bn1((1+eps)*h + agg) @ W1 + b1)) --------
// BM=128 BN=128 BK=8, 256 threads, 8x8 outputs/thread, FFMA2 inner loop.
__global__ __launch_bounds__(256) void k_gemm1(
    const float* __restrict__ W, const float* __restrict__ bias,
    const float* __restrict__ bg, const float* __restrict__ bb,
    const float* __restrict__ bm, const float* __restrict__ bv,
    const float* __restrict__ eps_l) {
    const int ALD = 132, BLD = 132;
    __shared__ __align__(16) float As[8 * 132];
    __shared__ __align__(16) float Bs[8 * 132];
    int t = threadIdx.x;
    int n0 = blockIdx.x * 128;
    int j0 = blockIdx.y * 128;
    int tx = t & 15, ty = t >> 4;
    float scale = 1.0f + __ldg(eps_l);

    int ar = t >> 1, askip = (t & 1) * 4;
    int an = n0 + ar;
    int bk = t >> 5, bj = (t & 31) * 4;

    unsigned long long acc[8][4];
#pragma unroll
    for (int i = 0; i < 8; i++)
#pragma unroll
        for (int j = 0; j < 4; j++) acc[i][j] = 0ULL;

    for (int k0 = 0; k0 < DD; k0 += 8) {
        float4 z4 = make_float4(0.f, 0.f, 0.f, 0.f);
        if (an < NN) {
            float4 h4 = *(const float4*)(g_h + (size_t)an * DD + k0 + askip);
            float4 a4 = *(const float4*)(g_agg + (size_t)an * DD + k0 + askip);
            z4.x = fmaf(scale, h4.x, a4.x);
            z4.y = fmaf(scale, h4.y, a4.y);
            z4.z = fmaf(scale, h4.z, a4.z);
            z4.w = fmaf(scale, h4.w, a4.w);
        }
        As[(askip + 0) * ALD + ar] = z4.x;
        As[(askip + 1) * ALD + ar] = z4.y;
        As[(askip + 2) * ALD + ar] = z4.z;
        As[(askip + 3) * ALD + ar] = z4.w;
        float4 w4 = *(const float4*)(W + (size_t)(k0 + bk) * D2 + j0 + bj);
        *(float4*)(Bs + bk * BLD + bj) = w4;
        __syncthreads();
#pragma unroll
        for (int k = 0; k < 8; k++) {
            float4 a0 = *(const float4*)(As + k * ALD + ty * 8);
            float4 a1 = *(const float4*)(As + k * ALD + ty * 8 + 4);
            float4 b0 = *(const float4*)(Bs + k * BLD + tx * 8);
            float4 b1 = *(const float4*)(Bs + k * BLD + tx * 8 + 4);
            unsigned long long pb[4];
            pb[0] = pk2(b0.x, b0.y); pb[1] = pk2(b0.z, b0.w);
            pb[2] = pk2(b1.x, b1.y); pb[3] = pk2(b1.z, b1.w);
            float av[8] = {a0.x, a0.y, a0.z, a0.w, a1.x, a1.y, a1.z, a1.w};
#pragma unroll
            for (int i = 0; i < 8; i++) {
                unsigned long long pa = rep2(av[i]);
                fma2(acc[i][0], pa, pb[0]);
                fma2(acc[i][1], pa, pb[1]);
                fma2(acc[i][2], pa, pb[2]);
                fma2(acc[i][3], pa, pb[3]);
            }
        }
        __syncthreads();
    }

    float cs[8], ct[8];
#pragma unroll
    for (int jj = 0; jj < 8; jj++) {
        int j = j0 + tx * 8 + jj;
        float s = bg[j] * rsqrtf(bv[j] + BNE);
        cs[jj] = s;
        ct[jj] = (bias[j] - bm[j]) * s + bb[j];
    }
#pragma unroll
    for (int i = 0; i < 8; i++) {
        int n = n0 + ty * 8 + i;
        if (n < NN) {
            float o[8];
#pragma unroll
            for (int p = 0; p < 4; p++) {
                float2 q = upk(acc[i][p]);
                o[2 * p] = q.x; o[2 * p + 1] = q.y;
            }
#pragma unroll
            for (int jj = 0; jj < 8; jj++)
                o[jj] = fmaxf(fmaf(o[jj], cs[jj], ct[jj]), 0.0f);
            float4* dst = (float4*)(g_y + (size_t)n * D2 + j0 + tx * 8);
            dst[0] = make_float4(o[0], o[1], o[2], o[3]);
            dst[1] = make_float4(o[4], o[5], o[6], o[7]);
        }
    }
}

// ---------------- GEMM2: h/out = [relu](bn(y @ W2 + b2)) -------------------
template <bool LAST>
__global__ __launch_bounds__(256) void k_gemm2(
    const float* __restrict__ W, const float* __restrict__ bias,
    const float* __restrict__ bg, const float* __restrict__ bb,
    const float* __restrict__ bm, const float* __restrict__ bv,
    float* __restrict__ outp) {
    const int ALD = 132, BLD = 132;
    __shared__ __align__(16) float As[8 * 132];
    __shared__ __align__(16) float Bs[8 * 132];
    int t = threadIdx.x;
    int n0 = blockIdx.x * 128;
    int tx = t & 15, ty = t >> 4;
    int ar = t >> 1, askip = (t & 1) * 4;
    int an = n0 + ar;
    int bk = t >> 5, bj = (t & 31) * 4;

    unsigned long long acc[8][4];
#pragma unroll
    for (int i = 0; i < 8; i++)
#pragma unroll
        for (int j = 0; j < 4; j++) acc[i][j] = 0ULL;

    for (int k0 = 0; k0 < D2; k0 += 8) {
        float4 z4 = make_float4(0.f, 0.f, 0.f, 0.f);
        if (an < NN)
            z4 = *(const float4*)(g_y + (size_t)an * D2 + k0 + askip);
        As[(askip + 0) * ALD + ar] = z4.x;
        As[(askip + 1) * ALD + ar] = z4.y;
        As[(askip + 2) * ALD + ar] = z4.z;
        As[(askip + 3) * ALD + ar] = z4.w;
        float4 w4 = *(const float4*)(W + (size_t)(k0 + bk) * DD + bj);
        *(float4*)(Bs + bk * BLD + bj) = w4;
        __syncthreads();
#pragma unroll
        for (int k = 0; k < 8; k++) {
            float4 a0 = *(const float4*)(As + k * ALD + ty * 8);
            float4 a1 = *(const float4*)(As + k * ALD + ty * 8 + 4);
            float4 b0 = *(const float4*)(Bs + k * BLD + tx * 8);
            float4 b1 = *(const float4*)(Bs + k * BLD + tx * 8 + 4);
            unsigned long long pb[4];
            pb[0] = pk2(b0.x, b0.y); pb[1] = pk2(b0.z, b0.w);
            pb[2] = pk2(b1.x, b1.y); pb[3] = pk2(b1.z, b1.w);
            float av[8] = {a0.x, a0.y, a0.z, a0.w, a1.x, a1.y, a1.z, a1.w};
#pragma unroll
            for (int i = 0; i < 8; i++) {
                unsigned long long pa = rep2(av[i]);
                fma2(acc[i][0], pa, pb[0]);
                fma2(acc[i][1], pa, pb[1]);
                fma2(acc[i][2], pa, pb[2]);
                fma2(acc[i][3], pa, pb[3]);
            }
        }
        __syncthreads();
    }

    float cs[8], ct[8];
#pragma unroll
    for (int jj = 0; jj < 8; jj++) {
        int j = tx * 8 + jj;
        float s = bg[j] * rsqrtf(bv[j] + BNE);
        cs[jj] = s;
        ct[jj] = (bias[j] - bm[j]) * s + bb[j];
    }
    float* base = LAST ? outp : g_h;
#pragma unroll
    for (int i = 0; i < 8; i++) {
        int n = n0 + ty * 8 + i;
        if (n < NN) {
            float o[8];
#pragma unroll
            for (int p = 0; p < 4; p++) {
                float2 q = upk(acc[i][p]);
                o[2 * p] = q.x; o[2 * p + 1] = q.y;
            }
#pragma unroll
            for (int jj = 0; jj < 8; jj++) {
                o[jj] = fmaf(o[jj], cs[jj], ct[jj]);
                if (!LAST) o[jj] = fmaxf(o[jj], 0.0f);
            }
            float4* dst = (float4*)(base + (size_t)n * DD + tx * 8);
            dst[0] = make_float4(o[0], o[1], o[2], o[3]);
            dst[1] = make_float4(o[4], o[5], o[6], o[7]);
        }
    }
}

// ---------------- virtual-node MLP (G=1024 rows, tiny) ---------------------
__global__ __launch_bounds__(256) void k_vnmlp1(
    const float* __restrict__ W, const float* __restrict__ bias,
    const float* __restrict__ bg, const float* __restrict__ bb,
    const float* __restrict__ bm, const float* __restrict__ bv) {
    __shared__ float xs[DD];
    int g = blockIdx.x, j = threadIdx.x;
    if (j < DD) xs[j] = g_vt[g * DD + j] + g_vn[g * DD + j];  // VP = 1.0
    __syncthreads();
    float acc = 0.0f;
#pragma unroll 8
    for (int k = 0; k < DD; ++k) acc = fmaf(xs[k], __ldg(&W[k * D2 + j]), acc);
    acc += bias[j];
    float s = bg[j] * rsqrtf(bv[j] + BNE);
    g_t[g * D2 + j] = fmaxf((acc - bm[j]) * s + bb[j], 0.0f);
}

__global__ __launch_bounds__(128) void k_vnmlp2(
    const float* __restrict__ W, const float* __restrict__ bias,
    const float* __restrict__ bg, const float* __restrict__ bb,
    const float* __restrict__ bm, const float* __restrict__ bv) {
    __shared__ float ts[D2];
    int g = blockIdx.x, d = threadIdx.x;
    ts[d] = g_t[g * D2 + d];
    ts[d + DD] = g_t[g * D2 + d + DD];
    __syncthreads();
    float acc = 0.0f;
#pragma unroll 8
    for (int k = 0; k < D2; ++k) acc = fmaf(ts[k], __ldg(&W[k * DD + d]), acc);
    acc += bias[d];
    float s = bg[d] * rsqrtf(bv[d] + BNE);
    g_vn[g * DD + d] = fmaxf((acc - bm[d]) * s + bb[d], 0.0f);
}

// ---------------- launch ---------------------------------------------------
extern "C" void kernel_launch(void* const* d_in, const int* in_sizes, int n_in,
                              void* d_out, int out_size) {
    const int* x_atom     = (const int*)d_in[0];
    const int* edge_index = (const int*)d_in[1];
    const int* edge_attr  = (const int*)d_in[2];
    const int* batch      = (const int*)d_in[3];
    const float* atom_emb = (const float*)d_in[4];
    const float* vn_emb0  = (const float*)d_in[5];
    const float* bond_emb = (const float*)d_in[6];
    const float* eps      = (const float*)d_in[7];
    const float* mW1  = (const float*)d_in[8];
    const float* mb1  = (const float*)d_in[9];
    const float* m1g  = (const float*)d_in[10];
    const float* m1b  = (const float*)d_in[11];
    const float* m1m  = (const float*)d_in[12];
    const float* m1v  = (const float*)d_in[13];
    const float* mW2  = (const float*)d_in[14];
    const float* mb2  = (const float*)d_in[15];
    const float* bng  = (const float*)d_in[16];
    const float* bnb  = (const float*)d_in[17];
    const float* bnm  = (const float*)d_in[18];
    const float* bnv  = (const float*)d_in[19];
    const float* vW1  = (const float*)d_in[20];
    const float* vb1  = (const float*)d_in[21];
    const float* v1g  = (const float*)d_in[22];
    const float* v1b  = (const float*)d_in[23];
    const float* v1m  = (const float*)d_in[24];
    const float* v1v  = (const float*)d_in[25];
    const float* vW2  = (const float*)d_in[26];
    const float* vb2  = (const float*)d_in[27];
    const float* v2g  = (const float*)d_in[28];
    const float* v2b  = (const float*)d_in[29];
    const float* v2m  = (const float*)d_in[30];
    const float* v2v  = (const float*)d_in[31];
    float* out = (float*)d_out;

    const int gemmRows = (NN + 127) / 128;  // 391

    k_vn_init<<<GG, DD>>>(vn_emb0);
    k_atom<<<NN, DD>>>(x_atom, atom_emb, vn_emb0, batch);

    for (int l = 0; l < LL; ++l) {
        if (l > 0) {
            if (l < LL - 1) {
                k_zero_vt<<<GG, DD>>>();
                k_add_vn<true><<<NN, DD>>>(batch);
            } else {
                k_add_vn<false><<<NN, DD>>>(batch);
            }
        }
        k_edge<<<EE / 8, 256>>>(edge_index, edge_attr,
                                bond_emb + (size_t)l * 3 * 10 * DD);
        k_gemm1<<<dim3(gemmRows, 2), 256>>>(
            mW1 + (size_t)l * DD * D2, mb1 + l * D2,
            m1g + l * D2, m1b + l * D2, m1m + l * D2, m1v + l * D2,
            eps + l);
        if (l < LL - 1) {
            k_gemm2<false><<<gemmRows, 256>>>(
                mW2 + (size_t)l * D2 * DD, mb2 + l * DD,
                bng + l * DD, bnb + l * DD, bnm + l * DD, bnv + l * DD,
                nullptr);
            k_vnmlp1<<<GG, D2>>>(
                vW1 + (size_t)l * DD * D2, vb1 + l * D2,
                v1g + l * D2, v1b + l * D2, v1m + l * D2, v1v + l * D2);
            k_vnmlp2<<<GG, DD>>>(
                vW2 + (size_t)l * D2 * DD, vb2 + l * DD,
                v2g + l * DD, v2b + l * DD, v2m + l * DD, v2v + l * DD);
        } else {
            k_gemm2<true><<<gemmRows, 256>>>(
                mW2 + (size_t)l * D2 * DD, mb2 + l * DD,
                bng + l * DD, bnb + l * DD, bnm + l * DD, bnv + l * DD,
                out);
        }
    }
}

// round 8
// speedup vs baseline: 1.1580x; 1.1580x over previous
#include <cuda_runtime.h>
#include <cstdint>

#define NN 50000
#define EE 800000
#define GG 1024
#define DD 128
#define D2 256
#define LL 3
#define BNE 1e-5f
#define CHUNK 196  // 196*256 = 50176 >= NN

// ---------------- scratch (device globals: no allocation allowed) ----------
__device__ __align__(128) float g_h[NN * DD];
__device__ __align__(128) float g_agg[NN * DD];
__device__ __align__(128) float g_y[NN * D2];
__device__ __align__(128) float g_vn[GG * DD];
__device__ __align__(128) float g_vt[GG * DD];
__device__ __align__(128) float g_t[GG * D2];
// CSR-by-dst (built once per launch; graph constant across layers)
__device__ int g_deg[NN];
__device__ int g_rowptr[NN + 1];
__device__ int g_cursor[NN];
__device__ int g_bsum[256];
__device__ __align__(16) int4 g_epack[EE];  // {src, a0, a1, a2} per edge, CSR order

// ---------------- packed f32x2 helpers (Blackwell FFMA2 via PTX) ----------
__device__ __forceinline__ unsigned long long pk2(float x, float y) {
    unsigned long long r;
    asm("mov.b64 %0, {%1, %2};" : "=l"(r)
        : "r"(__float_as_uint(x)), "r"(__float_as_uint(y)));
    return r;
}
__device__ __forceinline__ unsigned long long rep2(float x) {
    unsigned u = __float_as_uint(x);
    unsigned long long r;
    asm("mov.b64 %0, {%1, %1};" : "=l"(r) : "r"(u));
    return r;
}
__device__ __forceinline__ void fma2(unsigned long long& d, unsigned long long a,
                                     unsigned long long b) {
    asm("fma.rn.f32x2 %0, %1, %2, %0;" : "+l"(d) : "l"(a), "l"(b));
}
__device__ __forceinline__ float2 upk(unsigned long long p) {
    unsigned lo, hi;
    asm("mov.b64 {%0, %1}, %2;" : "=r"(lo), "=r"(hi) : "l"(p));
    return make_float2(__uint_as_float(lo), __uint_as_float(hi));
}

// ---------------- CSR build (once per launch) ------------------------------
__global__ void k_zero_deg() {
    int i = blockIdx.x * 256 + threadIdx.x;
    if (i < NN) g_deg[i] = 0;
}
__global__ void k_count(const int* __restrict__ eidx) {
    int e = blockIdx.x * 256 + threadIdx.x;
    if (e < EE) atomicAdd(&g_deg[__ldg(eidx + EE + e)], 1);
}
__global__ void k_chunk_sum() {
    __shared__ int s[256];
    int b = blockIdx.x, t = threadIdx.x;
    int idx = b * CHUNK + t;
    s[t] = (t < CHUNK && idx < NN) ? g_deg[idx] : 0;
    __syncthreads();
    for (int off = 128; off > 0; off >>= 1) {
        if (t < off) s[t] += s[t + off];
        __syncthreads();
    }
    if (t == 0) g_bsum[b] = s[0];
}
__global__ void k_scan_bsums() {
    __shared__ int s[256];
    int t = threadIdx.x;
    s[t] = g_bsum[t];
    __syncthreads();
    for (int off = 1; off < 256; off <<= 1) {
        int v = (t >= off) ? s[t - off] : 0;
        __syncthreads();
        s[t] += v;
        __syncthreads();
    }
    g_bsum[t] = (t == 0) ? 0 : s[t - 1];
}
__global__ void k_chunk_scan() {
    int b = blockIdx.x;
    if (threadIdx.x != 0) return;
    int run = g_bsum[b];
    int base = b * CHUNK;
    for (int i = 0; i < CHUNK; i++) {
        int idx = base + i;
        if (idx < NN) {
            g_rowptr[idx] = run;
            g_cursor[idx] = run;
            run += g_deg[idx];
        }
    }
    if (b == 255) g_rowptr[NN] = run;
}
// fill packed payload {src, a0, a1, a2} in CSR order
__global__ void k_fill(const int* __restrict__ eidx,
                       const int* __restrict__ eattr) {
    int e = blockIdx.x * 256 + threadIdx.x;
    if (e < EE) {
        int pos = atomicAdd(&g_cursor[__ldg(eidx + EE + e)], 1);
        int4 p;
        p.x = __ldg(eidx + e);
        p.y = __ldg(eattr + 3 * e);
        p.z = __ldg(eattr + 3 * e + 1);
        p.w = __ldg(eattr + 3 * e + 2);
        g_epack[pos] = p;
    }
}

// ---------------- small elementwise kernels --------------------------------
__global__ void k_vn_init(const float* __restrict__ vn_emb0) {
    int g = blockIdx.x, d = threadIdx.x;
    g_vn[g * DD + d] = vn_emb0[d];
    g_vt[g * DD + d] = 0.0f;
}
__global__ void k_zero_vt() {
    g_vt[blockIdx.x * DD + threadIdx.x] = 0.0f;
}

// atom encoder fused with layer-0 vn add + layer-0 segment sum
__global__ void k_atom(const int* __restrict__ x_atom,
                       const float* __restrict__ atom_emb,
                       const float* __restrict__ vn_emb0,
                       const int* __restrict__ batch) {
    int n = blockIdx.x, d = threadIdx.x;
    float s = vn_emb0[d];
#pragma unroll
    for (int f = 0; f < 9; ++f) {
        int idx = __ldg(&x_atom[n * 9 + f]);
        s += __ldg(&atom_emb[(f * 100 + idx) * DD + d]);
    }
    g_h[n * DD + d] = s;
    atomicAdd(&g_vt[__ldg(&batch[n]) * DD + d], s);
}

template <bool ACC_VT>
__global__ void k_add_vn(const int* __restrict__ batch) {
    int n = blockIdx.x, d = threadIdx.x;
    int b = __ldg(&batch[n]);
    float v = g_h[n * DD + d] + g_vn[b * DD + d];
    g_h[n * DD + d] = v;
    if (ACC_VT) atomicAdd(&g_vt[b * DD + d], v);
}

// ---------------- gather: one warp per dst node, packed payload, prefetch --
__global__ __launch_bounds__(256) void k_gather(const float* __restrict__ bond) {
    int n = (blockIdx.x * 256 + threadIdx.x) >> 5;
    if (n >= NN) return;
    int lane = threadIdx.x & 31;
    int beg = __ldg(&g_rowptr[n]);
    int end = __ldg(&g_rowptr[n + 1]);
    float4 acc = make_float4(0.f, 0.f, 0.f, 0.f);
    if (beg < end) {
        int4 p = *(const int4*)&g_epack[beg];
        for (int i = beg; i < end; i++) {
            int4 cur = p;
            if (i + 1 < end) p = *(const int4*)&g_epack[i + 1];
            float4 hv = *(const float4*)(g_h + (size_t)cur.x * DD + lane * 4);
            float4 e0 = *(const float4*)(bond + (size_t)(0 * 10 + cur.y) * DD + lane * 4);
            float4 e1 = *(const float4*)(bond + (size_t)(1 * 10 + cur.z) * DD + lane * 4);
            float4 e2 = *(const float4*)(bond + (size_t)(2 * 10 + cur.w) * DD + lane * 4);
            acc.x += fmaxf(hv.x + e0.x + e1.x + e2.x, 0.0f);
            acc.y += fmaxf(hv.y + e0.y + e1.y + e2.y, 0.0f);
            acc.z += fmaxf(hv.z + e0.z + e1.z + e2.z, 0.0f);
            acc.w += fmaxf(hv.w + e0.w + e1.w + e2.w, 0.0f);
        }
    }
    *(float4*)(g_agg + (size_t)n * DD + lane * 4) = acc;
}

// ---------------- GEMM1: y = relu(bn1((1+eps)*h + agg) @ W1 + b1)) --------
// BM=128 BN=128 BK=8; 4+4 split thread tile -> conflict-free LDS; prefetched.
__global__ __launch_bounds__(256) void k_gemm1(
    const float* __restrict__ W, const float* __restrict__ bias,
    const float* __restrict__ bg, const float* __restrict__ bb,
    const float* __restrict__ bm, const float* __restrict__ bv,
    const float* __restrict__ eps_l) {
    const int ALD = 132, BLD = 132;
    __shared__ __align__(16) float As[8 * 132];
    __shared__ __align__(16) float Bs[8 * 132];
    int t = threadIdx.x;
    int n0 = blockIdx.x * 128;
    int j0 = blockIdx.y * 128;
    int tx = t & 15, ty = t >> 4;
    float scale = 1.0f + __ldg(eps_l);

    int ar = t >> 1, askip = (t & 1) * 4;
    int an = n0 + ar;
    int bk = t >> 5, bj = (t & 31) * 4;

    unsigned long long acc[8][4];
#pragma unroll
    for (int i = 0; i < 8; i++)
#pragma unroll
        for (int j = 0; j < 4; j++) acc[i][j] = 0ULL;

    // prefetch iter 0
    float4 z4 = make_float4(0.f, 0.f, 0.f, 0.f), w4;
    if (an < NN) {
        float4 h4 = *(const float4*)(g_h + (size_t)an * DD + askip);
        float4 a4 = *(const float4*)(g_agg + (size_t)an * DD + askip);
        z4.x = fmaf(scale, h4.x, a4.x);
        z4.y = fmaf(scale, h4.y, a4.y);
        z4.z = fmaf(scale, h4.z, a4.z);
        z4.w = fmaf(scale, h4.w, a4.w);
    }
    w4 = *(const float4*)(W + (size_t)bk * D2 + j0 + bj);

    for (int k0 = 0; k0 < DD; k0 += 8) {
        As[(askip + 0) * ALD + ar] = z4.x;
        As[(askip + 1) * ALD + ar] = z4.y;
        As[(askip + 2) * ALD + ar] = z4.z;
        As[(askip + 3) * ALD + ar] = z4.w;
        *(float4*)(Bs + bk * BLD + bj) = w4;
        __syncthreads();
        if (k0 + 8 < DD) {
            int kn = k0 + 8;
            z4 = make_float4(0.f, 0.f, 0.f, 0.f);
            if (an < NN) {
                float4 h4 = *(const float4*)(g_h + (size_t)an * DD + kn + askip);
                float4 a4 = *(const float4*)(g_agg + (size_t)an * DD + kn + askip);
                z4.x = fmaf(scale, h4.x, a4.x);
                z4.y = fmaf(scale, h4.y, a4.y);
                z4.z = fmaf(scale, h4.z, a4.z);
                z4.w = fmaf(scale, h4.w, a4.w);
            }
            w4 = *(const float4*)(W + (size_t)(kn + bk) * D2 + j0 + bj);
        }
#pragma unroll
        for (int k = 0; k < 8; k++) {
            float4 a0 = *(const float4*)(As + k * ALD + ty * 4);
            float4 a1 = *(const float4*)(As + k * ALD + 64 + ty * 4);
            float4 b0 = *(const float4*)(Bs + k * BLD + tx * 4);
            float4 b1 = *(const float4*)(Bs + k * BLD + 64 + tx * 4);
            unsigned long long pb[4];
            pb[0] = pk2(b0.x, b0.y); pb[1] = pk2(b0.z, b0.w);
            pb[2] = pk2(b1.x, b1.y); pb[3] = pk2(b1.z, b1.w);
            float av[8] = {a0.x, a0.y, a0.z, a0.w, a1.x, a1.y, a1.z, a1.w};
#pragma unroll
            for (int i = 0; i < 8; i++) {
                unsigned long long pa = rep2(av[i]);
                fma2(acc[i][0], pa, pb[0]);
                fma2(acc[i][1], pa, pb[1]);
                fma2(acc[i][2], pa, pb[2]);
                fma2(acc[i][3], pa, pb[3]);
            }
        }
        __syncthreads();
    }

    float cs[8], ct[8];
#pragma unroll
    for (int jj = 0; jj < 8; jj++) {
        int j = j0 + ((jj < 4) ? (tx * 4 + jj) : (64 + tx * 4 + jj - 4));
        float s = bg[j] * rsqrtf(bv[j] + BNE);
        cs[jj] = s;
        ct[jj] = (bias[j] - bm[j]) * s + bb[j];
    }
#pragma unroll
    for (int i = 0; i < 8; i++) {
        int n = n0 + ((i < 4) ? (ty * 4 + i) : (64 + ty * 4 + i - 4));
        if (n < NN) {
            float o[8];
#pragma unroll
            for (int p = 0; p < 4; p++) {
                float2 q = upk(acc[i][p]);
                o[2 * p] = q.x; o[2 * p + 1] = q.y;
            }
#pragma unroll
            for (int jj = 0; jj < 8; jj++)
                o[jj] = fmaxf(fmaf(o[jj], cs[jj], ct[jj]), 0.0f);
            *(float4*)(g_y + (size_t)n * D2 + j0 + tx * 4) =
                make_float4(o[0], o[1], o[2], o[3]);
            *(float4*)(g_y + (size_t)n * D2 + j0 + 64 + tx * 4) =
                make_float4(o[4], o[5], o[6], o[7]);
        }
    }
}

// ---------------- GEMM2: h/out = [relu](bn(y @ W2 + b2)) -------------------
template <bool LAST>
__global__ __launch_bounds__(256) void k_gemm2(
    const float* __restrict__ W, const float* __restrict__ bias,
    const float* __restrict__ bg, const float* __restrict__ bb,
    const float* __restrict__ bm, const float* __restrict__ bv,
    float* __restrict__ outp) {
    const int ALD = 132, BLD = 132;
    __shared__ __align__(16) float As[8 * 132];
    __shared__ __align__(16) float Bs[8 * 132];
    int t = threadIdx.x;
    int n0 = blockIdx.x * 128;
    int tx = t & 15, ty = t >> 4;
    int ar = t >> 1, askip = (t & 1) * 4;
    int an = n0 + ar;
    int bk = t >> 5, bj = (t & 31) * 4;

    unsigned long long acc[8][4];
#pragma unroll
    for (int i = 0; i < 8; i++)
#pragma unroll
        for (int j = 0; j < 4; j++) acc[i][j] = 0ULL;

    float4 z4 = make_float4(0.f, 0.f, 0.f, 0.f), w4;
    if (an < NN) z4 = *(const float4*)(g_y + (size_t)an * D2 + askip);
    w4 = *(const float4*)(W + (size_t)bk * DD + bj);

    for (int k0 = 0; k0 < D2; k0 += 8) {
        As[(askip + 0) * ALD + ar] = z4.x;
        As[(askip + 1) * ALD + ar] = z4.y;
        As[(askip + 2) * ALD + ar] = z4.z;
        As[(askip + 3) * ALD + ar] = z4.w;
        *(float4*)(Bs + bk * BLD + bj) = w4;
        __syncthreads();
        if (k0 + 8 < D2) {
            int kn = k0 + 8;
            z4 = make_float4(0.f, 0.f, 0.f, 0.f);
            if (an < NN) z4 = *(const float4*)(g_y + (size_t)an * D2 + kn + askip);
            w4 = *(const float4*)(W + (size_t)(kn + bk) * DD + bj);
        }
#pragma unroll
        for (int k = 0; k < 8; k++) {
            float4 a0 = *(const float4*)(As + k * ALD + ty * 4);
            float4 a1 = *(const float4*)(As + k * ALD + 64 + ty * 4);
            float4 b0 = *(const float4*)(Bs + k * BLD + tx * 4);
            float4 b1 = *(const float4*)(Bs + k * BLD + 64 + tx * 4);
            unsigned long long pb[4];
            pb[0] = pk2(b0.x, b0.y); pb[1] = pk2(b0.z, b0.w);
            pb[2] = pk2(b1.x, b1.y); pb[3] = pk2(b1.z, b1.w);
            float av[8] = {a0.x, a0.y, a0.z, a0.w, a1.x, a1.y, a1.z, a1.w};
#pragma unroll
            for (int i = 0; i < 8; i++) {
                unsigned long long pa = rep2(av[i]);
                fma2(acc[i][0], pa, pb[0]);
                fma2(acc[i][1], pa, pb[1]);
                fma2(acc[i][2], pa, pb[2]);
                fma2(acc[i][3], pa, pb[3]);
            }
        }
        __syncthreads();
    }

    float cs[8], ct[8];
#pragma unroll
    for (int jj = 0; jj < 8; jj++) {
        int j = (jj < 4) ? (tx * 4 + jj) : (64 + tx * 4 + jj - 4);
        float s = bg[j] * rsqrtf(bv[j] + BNE);
        cs[jj] = s;
        ct[jj] = (bias[j] - bm[j]) * s + bb[j];
    }
    float* base = LAST ? outp : g_h;
#pragma unroll
    for (int i = 0; i < 8; i++) {
        int n = n0 + ((i < 4) ? (ty * 4 + i) : (64 + ty * 4 + i - 4));
        if (n < NN) {
            float o[8];
#pragma unroll
            for (int p = 0; p < 4; p++) {
                float2 q = upk(acc[i][p]);
                o[2 * p] = q.x; o[2 * p + 1] = q.y;
            }
#pragma unroll
            for (int jj = 0; jj < 8; jj++) {
                o[jj] = fmaf(o[jj], cs[jj], ct[jj]);
                if (!LAST) o[jj] = fmaxf(o[jj], 0.0f);
            }
            *(float4*)(base + (size_t)n * DD + tx * 4) =
                make_float4(o[0], o[1], o[2], o[3]);
            *(float4*)(base + (size_t)n * DD + 64 + tx * 4) =
                make_float4(o[4], o[5], o[6], o[7]);
        }
    }
}

// ---------------- virtual-node MLP (G=1024 rows, tiny) ---------------------
__global__ __launch_bounds__(256) void k_vnmlp1(
    const float* __restrict__ W, const float* __restrict__ bias,
    const float* __restrict__ bg, const float* __restrict__ bb,
    const float* __restrict__ bm, const float* __restrict__ bv) {
    __shared__ float xs[DD];
    int g = blockIdx.x, j = threadIdx.x;
    if (j < DD) xs[j] = g_vt[g * DD + j] + g_vn[g * DD + j];  // VP = 1.0
    __syncthreads();
    float acc = 0.0f;
#pragma unroll 8
    for (int k = 0; k < DD; ++k) acc = fmaf(xs[k], __ldg(&W[k * D2 + j]), acc);
    acc += bias[j];
    float s = bg[j] * rsqrtf(bv[j] + BNE);
    g_t[g * D2 + j] = fmaxf((acc - bm[j]) * s + bb[j], 0.0f);
}

__global__ __launch_bounds__(128) void k_vnmlp2(
    const float* __restrict__ W, const float* __restrict__ bias,
    const float* __restrict__ bg, const float* __restrict__ bb,
    const float* __restrict__ bm, const float* __restrict__ bv) {
    __shared__ float ts[D2];
    int g = blockIdx.x, d = threadIdx.x;
    ts[d] = g_t[g * D2 + d];
    ts[d + DD] = g_t[g * D2 + d + DD];
    __syncthreads();
    float acc = 0.0f;
#pragma unroll 8
    for (int k = 0; k < D2; ++k) acc = fmaf(ts[k], __ldg(&W[k * DD + d]), acc);
    acc += bias[d];
    float s = bg[d] * rsqrtf(bv[d] + BNE);
    g_vn[g * DD + d] = fmaxf((acc - bm[d]) * s + bb[d], 0.0f);
}

// ---------------- launch ---------------------------------------------------
extern "C" void kernel_launch(void* const* d_in, const int* in_sizes, int n_in,
                              void* d_out, int out_size) {
    const int* x_atom     = (const int*)d_in[0];
    const int* edge_index = (const int*)d_in[1];
    const int* edge_attr  = (const int*)d_in[2];
    const int* batch      = (const int*)d_in[3];
    const float* atom_emb = (const float*)d_in[4];
    const float* vn_emb0  = (const float*)d_in[5];
    const float* bond_emb = (const float*)d_in[6];
    const float* eps      = (const float*)d_in[7];
    const float* mW1  = (const float*)d_in[8];
    const float* mb1  = (const float*)d_in[9];
    const float* m1g  = (const float*)d_in[10];
    const float* m1b  = (const float*)d_in[11];
    const float* m1m  = (const float*)d_in[12];
    const float* m1v  = (const float*)d_in[13];
    const float* mW2  = (const float*)d_in[14];
    const float* mb2  = (const float*)d_in[15];
    const float* bng  = (const float*)d_in[16];
    const float* bnb  = (const float*)d_in[17];
    const float* bnm  = (const float*)d_in[18];
    const float* bnv  = (const float*)d_in[19];
    const float* vW1  = (const float*)d_in[20];
    const float* vb1  = (const float*)d_in[21];
    const float* v1g  = (const float*)d_in[22];
    const float* v1b  = (const float*)d_in[23];
    const float* v1m  = (const float*)d_in[24];
    const float* v1v  = (const float*)d_in[25];
    const float* vW2  = (const float*)d_in[26];
    const float* vb2  = (const float*)d_in[27];
    const float* v2g  = (const float*)d_in[28];
    const float* v2b  = (const float*)d_in[29];
    const float* v2m  = (const float*)d_in[30];
    const float* v2v  = (const float*)d_in[31];
    float* out = (float*)d_out;

    const int gemmRows = (NN + 127) / 128;  // 391

    // CSR build (graph constant across layers)
    k_zero_deg<<<(NN + 255) / 256, 256>>>();
    k_count<<<(EE + 255) / 256, 256>>>(edge_index);
    k_chunk_sum<<<256, 256>>>();
    k_scan_bsums<<<1, 256>>>();
    k_chunk_scan<<<256, 32>>>();
    k_fill<<<(EE + 255) / 256, 256>>>(edge_index, edge_attr);

    k_vn_init<<<GG, DD>>>(vn_emb0);
    k_atom<<<NN, DD>>>(x_atom, atom_emb, vn_emb0, batch);

    for (int l = 0; l < LL; ++l) {
        if (l > 0) {
            if (l < LL - 1) {
                k_zero_vt<<<GG, DD>>>();
                k_add_vn<true><<<NN, DD>>>(batch);
            } else {
                k_add_vn<false><<<NN, DD>>>(batch);
            }
        }
        k_gather<<<(NN * 32 + 255) / 256, 256>>>(bond_emb + (size_t)l * 3 * 10 * DD);
        k_gemm1<<<dim3(gemmRows, 2), 256>>>(
            mW1 + (size_t)l * DD * D2, mb1 + l * D2,
            m1g + l * D2, m1b + l * D2, m1m + l * D2, m1v + l * D2,
            eps + l);
        if (l < LL - 1) {
            k_gemm2<false><<<gemmRows, 256>>>(
                mW2 + (size_t)l * D2 * DD, mb2 + l * DD,
                bng + l * DD, bnb + l * DD, bnm + l * DD, bnv + l * DD,
                nullptr);
            k_vnmlp1<<<GG, D2>>>(
                vW1 + (size_t)l * DD * D2, vb1 + l * D2,
                v1g + l * D2, v1b + l * D2, v1m + l * D2, v1v + l * D2);
            k_vnmlp2<<<GG, DD>>>(
                vW2 + (size_t)l * D2 * DD, vb2 + l * DD,
                v2g + l * DD, v2b + l * DD, v2m + l * DD, v2v + l * DD);
        } else {
            k_gemm2<true><<<gemmRows, 256>>>(
                mW2 + (size_t)l * D2 * DD, mb2 + l * DD,
                bng + l * DD, bnb + l * DD, bnm + l * DD, bnv + l * DD,
                out);
        }
    }
}